// round 5
// baseline (speedup 1.0000x reference)
#include <cuda_runtime.h>
#include <cuda_bf16.h>

#define N_ATOMS   5000
#define N_EDGES   200000
#define N_TRIPLES 4000000
#define D_NODE    128
#define D_EDGE    128
#define N_BASIS   9

// Scratch (no allocations allowed)
__device__ float g_atoms[N_ATOMS * N_BASIS];        // sigmoid(node@W_atom+b)  [5000 x 9]
__device__ float g_new_bonds[N_EDGES * N_BASIS];    // segment sums            [200000 x 9]

// ---------------------------------------------------------------------------
// Kernel 0: zero the segment-sum accumulator
// ---------------------------------------------------------------------------
__global__ void zero_bonds_kernel() {
    int i = blockIdx.x * blockDim.x + threadIdx.x;
    const int n4 = (N_EDGES * N_BASIS) / 4;  // 450000
    if (i < n4) reinterpret_cast<float4*>(g_new_bonds)[i] = make_float4(0.f, 0.f, 0.f, 0.f);
}

// ---------------------------------------------------------------------------
// Kernel 1: atoms = sigmoid(node_feat @ W_atom + b_atom)   [5000 x 9]
// ---------------------------------------------------------------------------
__global__ void atoms_kernel(const float* __restrict__ node_feat,
                             const float* __restrict__ W_atom,
                             const float* __restrict__ b_atom) {
    int id = blockIdx.x * blockDim.x + threadIdx.x;
    if (id >= N_ATOMS * N_BASIS) return;
    int a = id / N_BASIS;
    int j = id % N_BASIS;
    float acc = b_atom[j];
    const float* nf = node_feat + a * D_NODE;
    #pragma unroll 8
    for (int k = 0; k < D_NODE; k++)
        acc = fmaf(nf[k], W_atom[k * N_BASIS + j], acc);
    g_atoms[id] = 1.0f / (1.0f + __expf(-acc));
}

// ---------------------------------------------------------------------------
// Kernel 2 (v3): coalesced staging with CONFLICT-FREE smem layout.
//
// Warp processes 512 contiguous triples per chunk in 8 passes of 64.
// Lane owns 2 triples per pass. Pass data (576 floats) is loaded with
// perfectly-coalesced float4 LDGs, scattered into the warp's smem slot in a
// stride-19 per-lane layout (gcd(19,32)=1 -> scalar readback conflict-free;
// scatter writes ~deg 2). Run-accumulation over sorted segment_ids persists
// across passes/chunks (merging across equal ids is always correct since the
// flush is an atomicAdd).
//
// smem: fp32 atoms 180000 B + 16 warp slots * 2432 B = 218912 B, 16 warps/SM.
// ---------------------------------------------------------------------------
#define TPB_T     512                        // 16 warps
#define WARPS_PB  (TPB_T / 32)
#define GRID_T    148
#define NWARPS_T  (GRID_T * WARPS_PB)        // 2368
#define WCHUNK    512
#define NWC       ((N_TRIPLES + WCHUNK - 1) / WCHUNK)   // 7813 (last = 256)
#define PASS_T    64                         // triples per pass
#define SLOT_STRIDE 19                       // floats per lane (18 data + 1 pad)
#define SLOT_F    (32 * SLOT_STRIDE)         // 608 floats = 2432 B
#define SMEM_T_BYTES ((N_ATOMS * N_BASIS + WARPS_PB * SLOT_F) * 4)  // 218912

__global__ __launch_bounds__(TPB_T) void triples_kernel(
    const float* __restrict__ three_basis,
    const int*   __restrict__ graph_dst,
    const int*   __restrict__ lg_dst,
    const int*   __restrict__ seg_ids) {

    extern __shared__ float smem[];
    float* s_atoms = smem;                                        // 45000 floats
    float* slot = smem + N_ATOMS * N_BASIS + (threadIdx.x >> 5) * SLOT_F;

    for (int i = threadIdx.x; i < N_ATOMS * N_BASIS; i += TPB_T)
        s_atoms[i] = g_atoms[i];
    __syncthreads();

    const float4* tb4 = reinterpret_cast<const float4*>(three_basis);
    const int2*   lg2 = reinterpret_cast<const int2*>(lg_dst);
    const int2*   sg2 = reinterpret_cast<const int2*>(seg_ids);

    const int lane = threadIdx.x & 31;
    const int warp_global = blockIdx.x * WARPS_PB + (threadIdx.x >> 5);

    float acc[N_BASIS];
    #pragma unroll
    for (int j = 0; j < N_BASIS; j++) acc[j] = 0.f;
    int cur = -1;

    // scatter helper: element e of the pass stream -> slot[(e/18)*19 + e%18]
    #define SCAT4(v4, ebase) do {                                            \
        int _e = (ebase);                                                    \
        slot[((_e    ) / 18) * SLOT_STRIDE + ((_e    ) % 18)] = (v4).x;      \
        slot[((_e + 1) / 18) * SLOT_STRIDE + ((_e + 1) % 18)] = (v4).y;      \
        slot[((_e + 2) / 18) * SLOT_STRIDE + ((_e + 2) % 18)] = (v4).z;      \
        slot[((_e + 3) / 18) * SLOT_STRIDE + ((_e + 3) % 18)] = (v4).w;      \
    } while (0)

    for (int wc = warp_global; wc < NWC; wc += NWARPS_T) {
        const int base = wc * WCHUNK;
        const int np = (N_TRIPLES - base) >= WCHUNK ? 8 : 4;  // 4M%512=256

        for (int s = 0; s < np; s++) {
            const int pbase = base + s * PASS_T;

            // coalesced streaming loads: 144 float4 (576 floats) per pass
            const float4* src = tb4 + (size_t)(pbase / 4) * 9;
            float4 v0 = src[lane];
            float4 v1 = src[lane + 32];
            float4 v2 = src[lane + 64];
            float4 v3 = src[lane + 96];
            float4 v4;
            if (lane < 16) v4 = src[lane + 128];

            int2 lg = lg2[pbase / 2 + lane];   // coalesced
            int2 sg = sg2[pbase / 2 + lane];

            __syncwarp();   // previous pass's readers done before overwrite
            SCAT4(v0, 4 * lane);
            SCAT4(v1, 4 * lane + 128);
            SCAT4(v2, 4 * lane + 256);
            SCAT4(v3, 4 * lane + 384);
            if (lane < 16) SCAT4(v4, 4 * lane + 512);
            __syncwarp();

            // scattered atom-index gathers (L2-resident)
            int ei0 = __ldg(graph_dst + lg.x);
            int ei1 = __ldg(graph_dst + lg.y);

            const float* myv = slot + lane * SLOT_STRIDE;  // conflict-free reads

            // triple 0 of this lane
            {
                int e = sg.x;
                if (e != cur) {
                    if (cur >= 0) {
                        float* dst = g_new_bonds + (size_t)cur * N_BASIS;
                        #pragma unroll
                        for (int j = 0; j < N_BASIS; j++) atomicAdd(dst + j, acc[j]);
                        #pragma unroll
                        for (int j = 0; j < N_BASIS; j++) acc[j] = 0.f;
                    }
                    cur = e;
                }
                const float* arow = s_atoms + ei0 * N_BASIS;
                #pragma unroll
                for (int j = 0; j < N_BASIS; j++)
                    acc[j] = fmaf(myv[j], arow[j], acc[j]);
            }
            // triple 1 of this lane
            {
                int e = sg.y;
                if (e != cur) {
                    if (cur >= 0) {
                        float* dst = g_new_bonds + (size_t)cur * N_BASIS;
                        #pragma unroll
                        for (int j = 0; j < N_BASIS; j++) atomicAdd(dst + j, acc[j]);
                        #pragma unroll
                        for (int j = 0; j < N_BASIS; j++) acc[j] = 0.f;
                    }
                    cur = e;
                }
                const float* arow = s_atoms + ei1 * N_BASIS;
                #pragma unroll
                for (int j = 0; j < N_BASIS; j++)
                    acc[j] = fmaf(myv[9 + j], arow[j], acc[j]);
            }
        }
    }
    #undef SCAT4

    // final flush
    if (cur >= 0) {
        float* dst = g_new_bonds + (size_t)cur * N_BASIS;
        #pragma unroll
        for (int j = 0; j < N_BASIS; j++) atomicAdd(dst + j, acc[j]);
    }
}

// ---------------------------------------------------------------------------
// Kernel 3: out = edge_feat + silu(g)*sigmoid(s),  g=nb@Wg+bg, s=nb@Ws+bs
// Persistent; fused-denominator sigmoid pair:
//   silu(g)*sigmoid(s) = g / ((1+e^-g)(1+e^-s))   -> 3 MUFU instead of 4.
// ---------------------------------------------------------------------------
#define E_TILE   64
#define NB_TILE  (E_TILE * N_BASIS)            // 576 floats
#define N_TILES  (N_EDGES / E_TILE)            // 3125
#define MLP_GRID 1184                          // 8 blocks/SM * 148

__global__ __launch_bounds__(D_EDGE) void mlp_kernel(
    const float* __restrict__ edge_feat,
    const float* __restrict__ W_gate, const float* __restrict__ b_gate,
    const float* __restrict__ W_sig,  const float* __restrict__ b_sig,
    float* __restrict__ out) {

    __shared__ float s_nb[NB_TILE];

    const int j = threadIdx.x;

    float wg[N_BASIS], ws[N_BASIS];
    #pragma unroll
    for (int k = 0; k < N_BASIS; k++) {
        wg[k] = W_gate[k * D_EDGE + j];
        ws[k] = W_sig [k * D_EDGE + j];
    }
    const float bg = b_gate[j];
    const float bs = b_sig[j];

    for (int tile = blockIdx.x; tile < N_TILES; tile += MLP_GRID) {
        const int e0 = tile * E_TILE;

        __syncthreads();
        const float* nb_src = g_new_bonds + (size_t)e0 * N_BASIS;
        #pragma unroll
        for (int i = j; i < NB_TILE; i += D_EDGE)
            s_nb[i] = nb_src[i];
        __syncthreads();

        #pragma unroll 2
        for (int e = 0; e < E_TILE; e += 2) {
            const float* nb0 = s_nb + e * N_BASIS;
            const float* nb1 = nb0 + N_BASIS;

            size_t idx0 = (size_t)(e0 + e) * D_EDGE + j;
            size_t idx1 = idx0 + D_EDGE;
            float ef0 = edge_feat[idx0];
            float ef1 = edge_feat[idx1];

            float g0 = bg, s0 = bs, g1 = bg, s1 = bs;
            #pragma unroll
            for (int k = 0; k < N_BASIS; k++) {
                float n0 = nb0[k], n1 = nb1[k];
                g0 = fmaf(n0, wg[k], g0);
                s0 = fmaf(n0, ws[k], s0);
                g1 = fmaf(n1, wg[k], g1);
                s1 = fmaf(n1, ws[k], s1);
            }
            // up = g / ((1+e^-g)(1+e^-s))  == silu(g)*sigmoid(s)
            float d0 = (1.f + __expf(-g0)) * (1.f + __expf(-s0));
            float d1 = (1.f + __expf(-g1)) * (1.f + __expf(-s1));
            out[idx0] = ef0 + __fdividef(g0, d0);
            out[idx1] = ef1 + __fdividef(g1, d1);
        }
    }
}

// ---------------------------------------------------------------------------
// Launch
// ---------------------------------------------------------------------------
extern "C" void kernel_launch(void* const* d_in, const int* in_sizes, int n_in,
                              void* d_out, int out_size) {
    const float* node_feat   = (const float*)d_in[0];
    const float* edge_feat   = (const float*)d_in[1];
    const float* three_basis = (const float*)d_in[2];
    const float* W_atom      = (const float*)d_in[4];
    const float* b_atom      = (const float*)d_in[5];
    const float* W_gate      = (const float*)d_in[6];
    const float* b_gate      = (const float*)d_in[7];
    const float* W_sig       = (const float*)d_in[8];
    const float* b_sig       = (const float*)d_in[9];
    const int*   graph_dst   = (const int*)d_in[10];
    const int*   lg_dst      = (const int*)d_in[12];
    const int*   seg_ids     = (const int*)d_in[13];
    float*       out         = (float*)d_out;

    cudaFuncSetAttribute(triples_kernel,
                         cudaFuncAttributeMaxDynamicSharedMemorySize, SMEM_T_BYTES);

    zero_bonds_kernel<<<(450000 + 255) / 256, 256>>>();
    atoms_kernel<<<(N_ATOMS * N_BASIS + 255) / 256, 256>>>(node_feat, W_atom, b_atom);
    triples_kernel<<<GRID_T, TPB_T, SMEM_T_BYTES>>>(three_basis, graph_dst, lg_dst, seg_ids);
    mlp_kernel<<<MLP_GRID, D_EDGE>>>(edge_feat, W_gate, b_gate, W_sig, b_sig, out);
}

// round 6
// speedup vs baseline: 1.0307x; 1.0307x over previous
#include <cuda_runtime.h>
#include <cuda_bf16.h>

#define N_ATOMS   5000
#define N_EDGES   200000
#define N_TRIPLES 4000000
#define D_NODE    128
#define D_EDGE    128
#define N_BASIS   9

// Scratch (no allocations allowed)
__device__ float g_atoms[N_ATOMS * N_BASIS];        // sigmoid(node@W_atom+b)  [5000 x 9]
__device__ float g_new_bonds[N_EDGES * N_BASIS];    // segment sums            [200000 x 9]

// ---------------------------------------------------------------------------
// Kernel 0: zero the segment-sum accumulator
// ---------------------------------------------------------------------------
__global__ void zero_bonds_kernel() {
    int i = blockIdx.x * blockDim.x + threadIdx.x;
    const int n4 = (N_EDGES * N_BASIS) / 4;  // 450000
    if (i < n4) reinterpret_cast<float4*>(g_new_bonds)[i] = make_float4(0.f, 0.f, 0.f, 0.f);
}

// ---------------------------------------------------------------------------
// Kernel 1: atoms = sigmoid(node_feat @ W_atom + b_atom)   [5000 x 9]
// ---------------------------------------------------------------------------
__global__ void atoms_kernel(const float* __restrict__ node_feat,
                             const float* __restrict__ W_atom,
                             const float* __restrict__ b_atom) {
    int id = blockIdx.x * blockDim.x + threadIdx.x;
    if (id >= N_ATOMS * N_BASIS) return;
    int a = id / N_BASIS;
    int j = id % N_BASIS;
    float acc = b_atom[j];
    const float* nf = node_feat + a * D_NODE;
    #pragma unroll 8
    for (int k = 0; k < D_NODE; k++)
        acc = fmaf(nf[k], W_atom[k * N_BASIS + j], acc);
    g_atoms[id] = 1.0f / (1.0f + __expf(-acc));
}

// ---------------------------------------------------------------------------
// Kernel 2 (v4, COLUMN-PARALLEL — no transpose anywhere):
//
// 9 lanes form a group owning one triple at a time; lane holds basis column
// j = lane%9. 3 groups per warp (lanes 0..26) process 3 consecutive triples
// per step, so the warp's three_basis read is 27 CONSECUTIVE floats (~1
// wavefront / 3 triples). Group g of a warp-chunk handles triples
// base + 3k + g (k = 0..31): its subsequence is stride-3 over a contiguous
// range, so sorted segment_ids still give long per-group runs.
//
// Run accumulation is ONE scalar per lane; a flush is a single coalesced
// atomicAdd per lane (9 consecutive addresses per group).
//
// smem = fp32 atoms table only (180 KB) -> TPB 1024, 32 warps/SM.
// ---------------------------------------------------------------------------
#define TPB_T    1024
#define GRID_T   148
#define NWARPS_T (GRID_T * (TPB_T / 32))       // 4736
#define WCH      96                            // triples per warp-chunk
#define NWC      ((N_TRIPLES + WCH - 1) / WCH) // 41667
#define SMEM_T_BYTES (N_ATOMS * N_BASIS * 4)   // 180000

__global__ __launch_bounds__(TPB_T) void triples_kernel(
    const float* __restrict__ three_basis,
    const int*   __restrict__ graph_dst,
    const int*   __restrict__ lg_dst,
    const int*   __restrict__ seg_ids) {

    extern __shared__ float s_atoms[];   // 45000 floats
    for (int i = threadIdx.x; i < N_ATOMS * N_BASIS; i += TPB_T)
        s_atoms[i] = g_atoms[i];
    __syncthreads();

    const int lane = threadIdx.x & 31;
    if (lane >= 27) return;              // 27 active lanes per warp

    const int group = lane / 9;          // 0..2
    const int j     = lane - group * 9;  // basis column 0..8
    const int warp_global = blockIdx.x * (TPB_T / 32) + (threadIdx.x >> 5);

    float acc = 0.f;
    int   cur = -1;

    for (int wc = warp_global; wc < NWC; wc += NWARPS_T) {
        const int base = wc * WCH;

        #pragma unroll 4
        for (int k = 0; k < 32; k++) {
            const int t = base + 3 * k + group;
            if (t < N_TRIPLES) {
                // warp reads 27 consecutive floats -> ~1 wavefront / 3 triples
                float val = __ldg(three_basis + (size_t)base * 9 + 27 * k + lane);
                int   e   = __ldg(seg_ids + t);              // group-converged
                int   ei  = __ldg(graph_dst + __ldg(lg_dst + t));

                if (e != cur) {
                    if (cur >= 0)
                        atomicAdd(g_new_bonds + (size_t)cur * N_BASIS + j, acc);
                    acc = 0.f;
                    cur = e;
                }
                acc = fmaf(val, s_atoms[ei * N_BASIS + j], acc);
            }
        }
    }

    if (cur >= 0)
        atomicAdd(g_new_bonds + (size_t)cur * N_BASIS + j, acc);
}

// ---------------------------------------------------------------------------
// Kernel 3: out = edge_feat + silu(g)*sigmoid(s)  (unchanged from R5 best)
// ---------------------------------------------------------------------------
#define E_TILE   64
#define NB_TILE  (E_TILE * N_BASIS)            // 576 floats
#define N_TILES  (N_EDGES / E_TILE)            // 3125
#define MLP_GRID 1184                          // 8 blocks/SM * 148

__global__ __launch_bounds__(D_EDGE) void mlp_kernel(
    const float* __restrict__ edge_feat,
    const float* __restrict__ W_gate, const float* __restrict__ b_gate,
    const float* __restrict__ W_sig,  const float* __restrict__ b_sig,
    float* __restrict__ out) {

    __shared__ float s_nb[NB_TILE];

    const int j = threadIdx.x;

    float wg[N_BASIS], ws[N_BASIS];
    #pragma unroll
    for (int k = 0; k < N_BASIS; k++) {
        wg[k] = W_gate[k * D_EDGE + j];
        ws[k] = W_sig [k * D_EDGE + j];
    }
    const float bg = b_gate[j];
    const float bs = b_sig[j];

    for (int tile = blockIdx.x; tile < N_TILES; tile += MLP_GRID) {
        const int e0 = tile * E_TILE;

        __syncthreads();
        const float* nb_src = g_new_bonds + (size_t)e0 * N_BASIS;
        #pragma unroll
        for (int i = j; i < NB_TILE; i += D_EDGE)
            s_nb[i] = nb_src[i];
        __syncthreads();

        #pragma unroll 2
        for (int e = 0; e < E_TILE; e += 2) {
            const float* nb0 = s_nb + e * N_BASIS;
            const float* nb1 = nb0 + N_BASIS;

            size_t idx0 = (size_t)(e0 + e) * D_EDGE + j;
            size_t idx1 = idx0 + D_EDGE;
            float ef0 = edge_feat[idx0];
            float ef1 = edge_feat[idx1];

            float g0 = bg, s0 = bs, g1 = bg, s1 = bs;
            #pragma unroll
            for (int k = 0; k < N_BASIS; k++) {
                float n0 = nb0[k], n1 = nb1[k];
                g0 = fmaf(n0, wg[k], g0);
                s0 = fmaf(n0, ws[k], s0);
                g1 = fmaf(n1, wg[k], g1);
                s1 = fmaf(n1, ws[k], s1);
            }
            // up = g / ((1+e^-g)(1+e^-s)) == silu(g)*sigmoid(s)
            float d0 = (1.f + __expf(-g0)) * (1.f + __expf(-s0));
            float d1 = (1.f + __expf(-g1)) * (1.f + __expf(-s1));
            out[idx0] = ef0 + __fdividef(g0, d0);
            out[idx1] = ef1 + __fdividef(g1, d1);
        }
    }
}

// ---------------------------------------------------------------------------
// Launch
// ---------------------------------------------------------------------------
extern "C" void kernel_launch(void* const* d_in, const int* in_sizes, int n_in,
                              void* d_out, int out_size) {
    const float* node_feat   = (const float*)d_in[0];
    const float* edge_feat   = (const float*)d_in[1];
    const float* three_basis = (const float*)d_in[2];
    const float* W_atom      = (const float*)d_in[4];
    const float* b_atom      = (const float*)d_in[5];
    const float* W_gate      = (const float*)d_in[6];
    const float* b_gate      = (const float*)d_in[7];
    const float* W_sig       = (const float*)d_in[8];
    const float* b_sig       = (const float*)d_in[9];
    const int*   graph_dst   = (const int*)d_in[10];
    const int*   lg_dst      = (const int*)d_in[12];
    const int*   seg_ids     = (const int*)d_in[13];
    float*       out         = (float*)d_out;

    cudaFuncSetAttribute(triples_kernel,
                         cudaFuncAttributeMaxDynamicSharedMemorySize, SMEM_T_BYTES);

    zero_bonds_kernel<<<(450000 + 255) / 256, 256>>>();
    atoms_kernel<<<(N_ATOMS * N_BASIS + 255) / 256, 256>>>(node_feat, W_atom, b_atom);
    triples_kernel<<<GRID_T, TPB_T, SMEM_T_BYTES>>>(three_basis, graph_dst, lg_dst, seg_ids);
    mlp_kernel<<<MLP_GRID, D_EDGE>>>(edge_feat, W_gate, b_gate, W_sig, b_sig, out);
}

// round 7
// speedup vs baseline: 1.5192x; 1.4739x over previous
#include <cuda_runtime.h>
#include <cuda_bf16.h>

#define N_ATOMS   5000
#define N_EDGES   200000
#define N_TRIPLES 4000000
#define D_NODE    128
#define D_EDGE    128
#define N_BASIS   9

// Scratch (no allocations allowed)
__device__ float g_atoms[N_ATOMS * N_BASIS];      // sigmoid(node@W_atom+b) [5000 x 9]
__device__ float g_new_bonds[N_EDGES * N_BASIS];  // segment sums           [200000 x 9]
__device__ int   g_seg_start[N_EDGES + 1];        // run boundaries in sorted seg_ids

// ---------------------------------------------------------------------------
// Kernel 1: atoms = sigmoid(node_feat @ W_atom + b_atom)   [5000 x 9]
// ---------------------------------------------------------------------------
__global__ void atoms_kernel(const float* __restrict__ node_feat,
                             const float* __restrict__ W_atom,
                             const float* __restrict__ b_atom) {
    int id = blockIdx.x * blockDim.x + threadIdx.x;
    if (id >= N_ATOMS * N_BASIS) return;
    int a = id / N_BASIS;
    int j = id % N_BASIS;
    float acc = b_atom[j];
    const float* nf = node_feat + a * D_NODE;
    #pragma unroll 8
    for (int k = 0; k < D_NODE; k++)
        acc = fmaf(nf[k], W_atom[k * N_BASIS + j], acc);
    g_atoms[id] = 1.0f / (1.0f + __expf(-acc));
}

// ---------------------------------------------------------------------------
// Kernel 1b: seg_start[e] = lower_bound(seg_ids, e)  (seg_ids is sorted)
// ---------------------------------------------------------------------------
__global__ void seg_start_kernel(const int* __restrict__ seg_ids) {
    int e = blockIdx.x * blockDim.x + threadIdx.x;
    if (e > N_EDGES) return;
    if (e == N_EDGES) { g_seg_start[N_EDGES] = N_TRIPLES; return; }
    int lo = 0, hi = N_TRIPLES;
    while (lo < hi) {
        int mid = (lo + hi) >> 1;
        if (__ldg(seg_ids + mid) < e) lo = mid + 1; else hi = mid;
    }
    g_seg_start[e] = lo;
}

// ---------------------------------------------------------------------------
// Kernel 2 (v5, WARP-PER-EDGE, zero atomics, zero divergence):
//
// Warp owns edge e with triple run [s, s+len) (contiguous, from seg_start).
// Lanes 0..26: group g = lane/9 handles triple s+3k+g, column j = lane%9.
// Per step the warp loads three_basis[(s+3k)*9 + lane] -> 27 CONSECUTIVE
// floats (<=2 lines per 3 triples). Index loads are 9-lane converged.
// Per-lane scalar accumulator over the whole run; epilogue = 2 shuffles +
// one coalesced 9-float PLAIN store (no atomicAdd, no zero-init pass).
// Loop trip count is warp-uniform -> no divergence anywhere.
//
// smem = fp32 atoms table (180 KB); TPB 1024 -> 32 warps/SM.
// ---------------------------------------------------------------------------
#define TPB_T    1024
#define GRID_T   148
#define NWARPS_T (GRID_T * (TPB_T / 32))   // 4736
#define SMEM_T_BYTES (N_ATOMS * N_BASIS * 4)  // 180000

__global__ __launch_bounds__(TPB_T) void triples_kernel(
    const float* __restrict__ three_basis,
    const int*   __restrict__ graph_dst,
    const int*   __restrict__ lg_dst) {

    extern __shared__ float s_atoms[];   // 45000 floats
    for (int i = threadIdx.x; i < N_ATOMS * N_BASIS; i += TPB_T)
        s_atoms[i] = g_atoms[i];
    __syncthreads();

    const int lane   = threadIdx.x & 31;
    const int group  = lane / 9;               // 0,1,2 (3 for lanes 27..31)
    const int j      = lane - group * 9;       // basis column
    const bool active = (lane < 27);
    const int warp_global = blockIdx.x * (TPB_T / 32) + (threadIdx.x >> 5);

    for (int e = warp_global; e < N_EDGES; e += NWARPS_T) {
        const int s   = g_seg_start[e];
        const int len = g_seg_start[e + 1] - s;

        float acc = 0.f;
        for (int k = 0; k < len; k += 3) {          // warp-uniform bound
            const int t = s + k + group;
            if (active && (k + group) < len) {
                // 27 consecutive floats per warp step
                float val = __ldg(three_basis + (size_t)(s + k) * 9 + lane);
                int   ei  = __ldg(graph_dst + __ldg(lg_dst + t));  // converged
                acc = fmaf(val, s_atoms[ei * N_BASIS + j], acc);
            }
        }

        // reduce the 3 groups' partial sums onto lanes 0..8
        float a1 = __shfl_down_sync(0xFFFFFFFFu, acc, 9);
        float a2 = __shfl_down_sync(0xFFFFFFFFu, acc, 18);
        if (lane < N_BASIS)
            g_new_bonds[(size_t)e * N_BASIS + lane] = acc + a1 + a2;
    }
}

// ---------------------------------------------------------------------------
// Kernel 3: out = edge_feat + silu(g)*sigmoid(s)   (best measured version)
// ---------------------------------------------------------------------------
#define E_TILE   64
#define NB_TILE  (E_TILE * N_BASIS)            // 576 floats
#define N_TILES  (N_EDGES / E_TILE)            // 3125
#define MLP_GRID 1184                          // 8 blocks/SM * 148

__global__ __launch_bounds__(D_EDGE) void mlp_kernel(
    const float* __restrict__ edge_feat,
    const float* __restrict__ W_gate, const float* __restrict__ b_gate,
    const float* __restrict__ W_sig,  const float* __restrict__ b_sig,
    float* __restrict__ out) {

    __shared__ float s_nb[NB_TILE];

    const int j = threadIdx.x;

    float wg[N_BASIS], ws[N_BASIS];
    #pragma unroll
    for (int k = 0; k < N_BASIS; k++) {
        wg[k] = W_gate[k * D_EDGE + j];
        ws[k] = W_sig [k * D_EDGE + j];
    }
    const float bg = b_gate[j];
    const float bs = b_sig[j];

    for (int tile = blockIdx.x; tile < N_TILES; tile += MLP_GRID) {
        const int e0 = tile * E_TILE;

        __syncthreads();
        const float* nb_src = g_new_bonds + (size_t)e0 * N_BASIS;
        #pragma unroll
        for (int i = j; i < NB_TILE; i += D_EDGE)
            s_nb[i] = nb_src[i];
        __syncthreads();

        #pragma unroll 2
        for (int e = 0; e < E_TILE; e += 2) {
            const float* nb0 = s_nb + e * N_BASIS;
            const float* nb1 = nb0 + N_BASIS;

            size_t idx0 = (size_t)(e0 + e) * D_EDGE + j;
            size_t idx1 = idx0 + D_EDGE;
            float ef0 = edge_feat[idx0];
            float ef1 = edge_feat[idx1];

            float g0 = bg, s0 = bs, g1 = bg, s1 = bs;
            #pragma unroll
            for (int k = 0; k < N_BASIS; k++) {
                float n0 = nb0[k], n1 = nb1[k];
                g0 = fmaf(n0, wg[k], g0);
                s0 = fmaf(n0, ws[k], s0);
                g1 = fmaf(n1, wg[k], g1);
                s1 = fmaf(n1, ws[k], s1);
            }
            // up = g / ((1+e^-g)(1+e^-s)) == silu(g)*sigmoid(s)
            float d0 = (1.f + __expf(-g0)) * (1.f + __expf(-s0));
            float d1 = (1.f + __expf(-g1)) * (1.f + __expf(-s1));
            out[idx0] = ef0 + __fdividef(g0, d0);
            out[idx1] = ef1 + __fdividef(g1, d1);
        }
    }
}

// ---------------------------------------------------------------------------
// Launch
// ---------------------------------------------------------------------------
extern "C" void kernel_launch(void* const* d_in, const int* in_sizes, int n_in,
                              void* d_out, int out_size) {
    const float* node_feat   = (const float*)d_in[0];
    const float* edge_feat   = (const float*)d_in[1];
    const float* three_basis = (const float*)d_in[2];
    const float* W_atom      = (const float*)d_in[4];
    const float* b_atom      = (const float*)d_in[5];
    const float* W_gate      = (const float*)d_in[6];
    const float* b_gate      = (const float*)d_in[7];
    const float* W_sig       = (const float*)d_in[8];
    const float* b_sig       = (const float*)d_in[9];
    const int*   graph_dst   = (const int*)d_in[10];
    const int*   lg_dst      = (const int*)d_in[12];
    const int*   seg_ids     = (const int*)d_in[13];
    float*       out         = (float*)d_out;

    cudaFuncSetAttribute(triples_kernel,
                         cudaFuncAttributeMaxDynamicSharedMemorySize, SMEM_T_BYTES);

    atoms_kernel<<<(N_ATOMS * N_BASIS + 255) / 256, 256>>>(node_feat, W_atom, b_atom);
    seg_start_kernel<<<(N_EDGES + 1 + 255) / 256, 256>>>(seg_ids);
    triples_kernel<<<GRID_T, TPB_T, SMEM_T_BYTES>>>(three_basis, graph_dst, lg_dst);
    mlp_kernel<<<MLP_GRID, D_EDGE>>>(edge_feat, W_gate, b_gate, W_sig, b_sig, out);
}